// round 1
// baseline (speedup 1.0000x reference)
#include <cuda_runtime.h>
#include <cstdint>

// Correlation (FlowNet-style): D=4, S1=S2=1
// x1, x2: (4, 128, 256, 256) fp32 ; out: (4, 81, 256, 256) fp32
//
// Tiling: block computes TH=8 x TW=32 output pixels for ALL 81 displacements.
// Thread (wg, ty, ky): P=4 consecutive pixels along w, one ky row, all 9 kx.
// 36 fp32 accumulators/thread. Channels staged through smem in chunks of 8,
// double-buffered via cp.async (zfill gives the zero padding for free).

#define N_IMG   4
#define C_DIM   128
#define H_DIM   256
#define W_DIM   256
#define TH      8
#define TW      32
#define PPT     4          // pixels per thread along w
#define KD      9          // 2*D/S2+1
#define CB      8          // channels per stage
#define NSTAGE  (C_DIM / CB)   // 16

#define X2_ROWS   (TH + 8)     // 16
#define X2_STRIDE 48           // 40 used + pad to 16B multiple
#define X1_CH     (TH * TW)          // 256 floats / channel
#define X2_CH     (X2_ROWS * X2_STRIDE)  // 768 floats / channel
#define X1_STAGE  (CB * X1_CH)   // 2048
#define X2_STAGE  (CB * X2_CH)   // 6144
#define SMEM_FLOATS (2 * (X1_STAGE + X2_STAGE))   // 16384 -> 64KB

#define NTHREADS  (8 * 8 * 9)   // 576

__device__ __forceinline__ void cp_async16(uint32_t dst, const void* src, int src_size) {
    asm volatile("cp.async.cg.shared.global [%0], [%1], 16, %2;\n"
                 :: "r"(dst), "l"(src), "r"(src_size) : "memory");
}
__device__ __forceinline__ void cp_commit() {
    asm volatile("cp.async.commit_group;\n" ::: "memory");
}

__global__ void corr_kernel(const float* __restrict__ x1,
                            const float* __restrict__ x2,
                            float* __restrict__ out) {
    const int wg = threadIdx.x;   // 0..7  (w group, PPT pixels each)
    const int ty = threadIdx.y;   // 0..7  (output row within tile)
    const int ky = threadIdx.z;   // 0..8  (displacement row)
    const int tid = threadIdx.x + 8 * threadIdx.y + 64 * threadIdx.z; // 0..575

    const int w0 = blockIdx.x * TW;     // 0..224
    const int h0 = blockIdx.y * TH;     // 0..248
    const int n  = blockIdx.z;

    extern __shared__ float sm[];
    float* X1S = sm;                 // [2][X1_STAGE]
    float* X2S = sm + 2 * X1_STAGE;  // [2][X2_STAGE]

    const float* x1n = x1 + (size_t)n * C_DIM * H_DIM * W_DIM;
    const float* x2n = x2 + (size_t)n * C_DIM * H_DIM * W_DIM;

    float acc[PPT * KD];
    #pragma unroll
    for (int i = 0; i < PPT * KD; ++i) acc[i] = 0.0f;

    // ---- stage loader: CB channels of x1 tile + x2 halo tile ----
    // x2 tasks: CB * 16 rows * 10 float4 = 1280 ; x1 tasks: CB * 8 rows * 8 float4 = 512
    auto load_stage = [&](int s, int buf) {
        const int c0 = s * CB;
        float* x1d = X1S + buf * X1_STAGE;
        float* x2d = X2S + buf * X2_STAGE;
        for (int t = tid; t < 1792; t += NTHREADS) {
            if (t < 1280) {
                const int c   = t / 160;
                const int rem = t % 160;
                const int r   = rem / 10;   // 0..15
                const int v   = rem % 10;   // 0..9  (float4 chunk)
                const int hr  = h0 - 4 + r;
                const int gw  = w0 - 4 + v * 4;
                const bool ok = (hr >= 0) && (hr < H_DIM) && (gw >= 0) && (gw <= W_DIM - 4);
                const float* src = ok ? (x2n + ((size_t)(c0 + c) * H_DIM + hr) * W_DIM + gw)
                                      : x2n;
                uint32_t dst = (uint32_t)__cvta_generic_to_shared(
                    x2d + (c * X2_ROWS + r) * X2_STRIDE + v * 4);
                cp_async16(dst, src, ok ? 16 : 0);
            } else {
                const int t2  = t - 1280;
                const int c   = t2 / 64;
                const int rem = t2 % 64;
                const int r   = rem / 8;    // 0..7
                const int v   = rem % 8;    // float4 chunk
                const float* src = x1n + ((size_t)(c0 + c) * H_DIM + h0 + r) * W_DIM + w0 + v * 4;
                uint32_t dst = (uint32_t)__cvta_generic_to_shared(
                    x1d + (c * TW * TH / TH) * 0 + (c * TH + r) * TW + v * 4);
                cp_async16(dst, src, 16);
            }
        }
        cp_commit();
    };

    // ---- compute one stage (CB channels) from smem ----
    auto compute_stage = [&](int buf) {
        const float* x1b = X1S + buf * X1_STAGE + ty * TW + wg * PPT;
        const float* x2b = X2S + buf * X2_STAGE + (ty + ky) * X2_STRIDE + wg * PPT;
        #pragma unroll
        for (int c = 0; c < CB; ++c) {
            float4 a  = *reinterpret_cast<const float4*>(x1b + c * X1_CH);
            float4 b0 = *reinterpret_cast<const float4*>(x2b + c * X2_CH);
            float4 b1 = *reinterpret_cast<const float4*>(x2b + c * X2_CH + 4);
            float4 b2 = *reinterpret_cast<const float4*>(x2b + c * X2_CH + 8);
            const float av[4] = {a.x, a.y, a.z, a.w};
            const float v[12] = {b0.x, b0.y, b0.z, b0.w,
                                 b1.x, b1.y, b1.z, b1.w,
                                 b2.x, b2.y, b2.z, b2.w};
            #pragma unroll
            for (int p = 0; p < PPT; ++p) {
                #pragma unroll
                for (int kx = 0; kx < KD; ++kx) {
                    acc[p * KD + kx] = fmaf(av[p], v[p + kx], acc[p * KD + kx]);
                }
            }
        }
    };

    // ---- software pipeline: double-buffered channel stages ----
    load_stage(0, 0);
    #pragma unroll 1
    for (int s = 0; s < NSTAGE; ++s) {
        if (s + 1 < NSTAGE) {
            load_stage(s + 1, (s + 1) & 1);
            asm volatile("cp.async.wait_group 1;\n" ::: "memory");
        } else {
            asm volatile("cp.async.wait_group 0;\n" ::: "memory");
        }
        __syncthreads();
        compute_stage(s & 1);
        __syncthreads();
    }

    // ---- epilogue: scale by 1/C, float4 stores per (ky,kx) channel ----
    const float inv = 1.0f / (float)C_DIM;
    float* op = out + (((size_t)(n * 81 + ky * KD) * H_DIM + h0 + ty) * W_DIM + w0 + wg * PPT);
    #pragma unroll
    for (int kx = 0; kx < KD; ++kx) {
        float4 r;
        r.x = acc[0 * KD + kx] * inv;
        r.y = acc[1 * KD + kx] * inv;
        r.z = acc[2 * KD + kx] * inv;
        r.w = acc[3 * KD + kx] * inv;
        *reinterpret_cast<float4*>(op + (size_t)kx * (H_DIM * W_DIM)) = r;
    }
}

extern "C" void kernel_launch(void* const* d_in, const int* in_sizes, int n_in,
                              void* d_out, int out_size) {
    const float* x1 = (const float*)d_in[0];
    const float* x2 = (const float*)d_in[1];
    float* out = (float*)d_out;

    cudaFuncSetAttribute(corr_kernel, cudaFuncAttributeMaxDynamicSharedMemorySize,
                         SMEM_FLOATS * sizeof(float));

    dim3 block(8, 8, 9);                       // 576 threads
    dim3 grid(W_DIM / TW, H_DIM / TH, N_IMG);  // (8, 32, 4) = 1024 blocks
    corr_kernel<<<grid, block, SMEM_FLOATS * sizeof(float)>>>(x1, x2, out);
}